// round 10
// baseline (speedup 1.0000x reference)
#include <cuda_runtime.h>
#include <cooperative_groups.h>
#include <cstdint>

namespace cg = cooperative_groups;

#define BB 32
#define NN 4096
#define DD 768
#define KK 1024
#define CHUNK 512
#define NCHUNK 8
#define ROWS_PER_BLK 8

typedef unsigned long long u64;

__device__ int g_topk[BB * KK];

// Map float to uint with ascending unsigned order == ascending float order.
__device__ __forceinline__ unsigned f2ord(float f) {
    unsigned u = __float_as_uint(f);
    return (u & 0x80000000u) ? ~u : (u | 0x80000000u);
}

// ---------------------------------------------------------------------------
// Fused sort + rank-merge, one 8-CTA cluster per batch (32 clusters).
// CTA c of cluster b: sort 512-element chunk c descending by composite key
// (ord << 12) | (4095 - idx)  => jax.lax.top_k order (value desc, index asc;
// keys strictly distinct). Sorted run stays in local smem. cluster.sync(),
// then DSMEM-copy the 7 sibling runs into local smem and compute
// rank = t + sum_o count(peer_o > key) via 7 interleaved 9-step binary
// searches. Ranks are a permutation of 0..4095; write idx iff rank < 1024.
// No global scratch, no fences, no spin - cluster barrier does it all.
// ---------------------------------------------------------------------------
__global__ __launch_bounds__(512) __cluster_dims__(NCHUNK, 1, 1)
void sort_merge_cluster_kernel(const float* __restrict__ sig) {
    __shared__ u64 sorted[CHUNK];                 // my sorted run (peers read this)
    __shared__ u64 peers[(NCHUNK - 1) * CHUNK];   // local copies of sibling runs

    cg::cluster_group cluster = cg::this_cluster();
    const int c = (int)cluster.block_rank();      // chunk id within batch
    const int b = blockIdx.x >> 3;                // batch id
    const int t = threadIdx.x;

    // ---- Phase 1: bitonic sort (identical network to round 8) ----
    const int g = c * CHUNK + t;
    float v = sig[(size_t)b * NN + g];
    u64 r = ((u64)f2ord(v) << 12) | (u64)(4095 - g);

    #pragma unroll
    for (int k = 2; k <= CHUNK; k <<= 1) {
        #pragma unroll
        for (int j = k >> 1; j > 0; j >>= 1) {
            bool keep_max = (((t & k) == 0) == ((t & j) == 0));
            u64 o;
            if (j >= 32) {
                __syncthreads();
                sorted[t] = r;
                __syncthreads();
                o = sorted[t ^ j];
            } else {
                o = __shfl_xor_sync(0xffffffffu, r, j);
            }
            r = keep_max ? (r > o ? r : o) : (r < o ? r : o);
        }
    }

    sorted[t] = r;          // publish my sorted run in smem
    cluster.sync();         // all 8 runs of this batch are final + visible

    // ---- Phase 2: pull sibling runs via DSMEM (coalesced), then rank ----
    #pragma unroll
    for (int o = 0; o < NCHUNK - 1; o++) {
        int pc = o + (o >= c ? 1 : 0);
        const u64* peer = (const u64*)cluster.map_shared_rank((void*)sorted, pc);
        peers[o * CHUNK + t] = peer[t];
    }
    __syncthreads();        // my peers[] buffer complete

    int cnt[NCHUNK - 1];
    #pragma unroll
    for (int o = 0; o < NCHUNK - 1; o++) cnt[o] = 0;

    #pragma unroll
    for (int s = CHUNK / 2; s >= 1; s >>= 1) {
        #pragma unroll
        for (int o = 0; o < NCHUNK - 1; o++) {
            if (peers[o * CHUNK + cnt[o] + s - 1] > r) cnt[o] += s;
        }
    }

    int rank = t;
    #pragma unroll
    for (int o = 0; o < NCHUNK - 1; o++) rank += cnt[o];

    if (rank < KK)
        g_topk[b * KK + rank] = 4095 - (int)(r & 0xFFFu);

    cluster.sync();         // keep smem alive until all peers finished reading
}

// ---------------------------------------------------------------------------
// Gather (unchanged, ~28us wall = ~7.2TB/s effective, ~90% of HBM spec):
// 8 rows/CTA, 192 threads, one float4 column each, MLP=8.
// ---------------------------------------------------------------------------
__global__ __launch_bounds__(192) void gather_kernel(const float4* __restrict__ x,
                                                     float4* __restrict__ out) {
    const int base = blockIdx.x * ROWS_PER_BLK;
    const int tid  = threadIdx.x;

    const float4* srcs[ROWS_PER_BLK];
    #pragma unroll
    for (int r = 0; r < ROWS_PER_BLK; r++) {
        int row = base + r;
        int b   = row / (KK + 1);
        int rr  = row - b * (KK + 1);
        int src_row = (rr == 0) ? 0 : (1 + g_topk[b * KK + rr - 1]);
        srcs[r] = x + ((size_t)b * (NN + 1) + (size_t)src_row) * (DD / 4);
    }

    float4 vals[ROWS_PER_BLK];
    #pragma unroll
    for (int r = 0; r < ROWS_PER_BLK; r++)
        vals[r] = __ldcs(srcs[r] + tid);

    #pragma unroll
    for (int r = 0; r < ROWS_PER_BLK; r++)
        out[(size_t)(base + r) * (DD / 4) + tid] = vals[r];
}

extern "C" void kernel_launch(void* const* d_in, const int* in_sizes, int n_in,
                              void* d_out, int out_size) {
    const float* x   = (const float*)d_in[0];   // [B, N+1, D] fp32
    const float* sig = (const float*)d_in[1];   // [B, N] fp32
    (void)in_sizes; (void)n_in; (void)out_size;

    sort_merge_cluster_kernel<<<BB * NCHUNK, CHUNK>>>(sig);
    gather_kernel<<<BB * (KK + 1) / ROWS_PER_BLK, 192>>>((const float4*)x, (float4*)d_out);
}

// round 11
// speedup vs baseline: 1.0464x; 1.0464x over previous
#include <cuda_runtime.h>
#include <cstdint>

#define BB 32
#define NN 4096
#define DD 768
#define KK 1024
#define CHUNK 512
#define NCHUNK 8
#define ROWS_PER_BLK 8

typedef unsigned long long u64;

__device__ int g_topk[BB * KK];
__device__ u64 g_scratch[BB * NN];   // per-batch: 8 sorted descending chunks

// Map float to uint with ascending unsigned order == ascending float order.
__device__ __forceinline__ unsigned f2ord(float f) {
    unsigned u = __float_as_uint(f);
    return (u & 0x80000000u) ? ~u : (u | 0x80000000u);
}

// ---------------------------------------------------------------------------
// Kernel A (round-8 exact, measured 7.8us): CTA (b,c) sorts 512-element chunk
// c of batch b descending by composite key (ord << 12) | (4095 - idx)
// => jax.lax.top_k order (value desc, index asc). Keys strictly distinct.
// 1 key/thread, 512 threads, 256 CTAs = 4096 warps for latency hiding.
// ---------------------------------------------------------------------------
__global__ __launch_bounds__(512) void sort_chunk_kernel(const float* __restrict__ sig) {
    __shared__ u64 sm[CHUNK];
    const int b = blockIdx.x >> 3;
    const int c = blockIdx.x & 7;
    const int t = threadIdx.x;

    const int g = c * CHUNK + t;
    float v = sig[(size_t)b * NN + g];
    u64 r = ((u64)f2ord(v) << 12) | (u64)(4095 - g);

    #pragma unroll
    for (int k = 2; k <= CHUNK; k <<= 1) {
        #pragma unroll
        for (int j = k >> 1; j > 0; j >>= 1) {
            bool keep_max = (((t & k) == 0) == ((t & j) == 0));
            u64 o;
            if (j >= 32) {
                __syncthreads();
                sm[t] = r;
                __syncthreads();
                o = sm[t ^ j];
            } else {
                o = __shfl_xor_sync(0xffffffffu, r, j);
            }
            r = keep_max ? (r > o ? r : o) : (r < o ? r : o);
        }
    }

    g_scratch[(size_t)b * NN + g] = r;
}

// ---------------------------------------------------------------------------
// Kernel B (round-8 logic + PDL): rank-based merge. CTA (b,c): thread t owns
// element t of sorted chunk c; rank = t + sum over the other 7 chunks of
// count(key' > key) via 7 interleaved 9-step binary searches in smem.
// Launched with programmatic stream serialization: grid comes up while the
// sort drains; cudaGridDependencySynchronize() gates the g_scratch reads.
// ---------------------------------------------------------------------------
__global__ __launch_bounds__(512) void rank_merge_kernel() {
    __shared__ u64 sm[(NCHUNK - 1) * CHUNK];   // 7 x 512 keys = 28 KB
    const int b = blockIdx.x >> 3;
    const int c = blockIdx.x & 7;
    const int t = threadIdx.x;

    cudaGridDependencySynchronize();           // sort kernel fully complete

    const u64* base = g_scratch + (size_t)b * NN;

    #pragma unroll
    for (int o = 0; o < NCHUNK - 1; o++) {
        int oc = o + (o >= c ? 1 : 0);
        sm[o * CHUNK + t] = base[oc * CHUNK + t];
    }

    u64 key = base[c * CHUNK + t];
    __syncthreads();

    int cnt[NCHUNK - 1];
    #pragma unroll
    for (int o = 0; o < NCHUNK - 1; o++) cnt[o] = 0;

    #pragma unroll
    for (int s = CHUNK / 2; s >= 1; s >>= 1) {
        #pragma unroll
        for (int o = 0; o < NCHUNK - 1; o++) {
            if (sm[o * CHUNK + cnt[o] + s - 1] > key) cnt[o] += s;
        }
    }

    int rank = t;
    #pragma unroll
    for (int o = 0; o < NCHUNK - 1; o++) rank += cnt[o];

    if (rank < KK)
        g_topk[b * KK + rank] = 4095 - (int)(key & 0xFFFu);
}

// ---------------------------------------------------------------------------
// Gather (round-8 exact + PDL; ~28us wall = ~7.2TB/s effective, ~90% of spec):
// 8 rows/CTA, 192 threads, one float4 column each, MLP=8. Launch overlaps the
// merge's tail; sync gates the g_topk reads.
// ---------------------------------------------------------------------------
__global__ __launch_bounds__(192) void gather_kernel(const float4* __restrict__ x,
                                                     float4* __restrict__ out) {
    const int base = blockIdx.x * ROWS_PER_BLK;
    const int tid  = threadIdx.x;

    cudaGridDependencySynchronize();           // merge kernel fully complete

    const float4* srcs[ROWS_PER_BLK];
    #pragma unroll
    for (int r = 0; r < ROWS_PER_BLK; r++) {
        int row = base + r;
        int b   = row / (KK + 1);
        int rr  = row - b * (KK + 1);
        int src_row = (rr == 0) ? 0 : (1 + g_topk[b * KK + rr - 1]);
        srcs[r] = x + ((size_t)b * (NN + 1) + (size_t)src_row) * (DD / 4);
    }

    float4 vals[ROWS_PER_BLK];
    #pragma unroll
    for (int r = 0; r < ROWS_PER_BLK; r++)
        vals[r] = __ldcs(srcs[r] + tid);

    #pragma unroll
    for (int r = 0; r < ROWS_PER_BLK; r++)
        out[(size_t)(base + r) * (DD / 4) + tid] = vals[r];
}

extern "C" void kernel_launch(void* const* d_in, const int* in_sizes, int n_in,
                              void* d_out, int out_size) {
    const float* x   = (const float*)d_in[0];   // [B, N+1, D] fp32
    const float* sig = (const float*)d_in[1];   // [B, N] fp32
    (void)in_sizes; (void)n_in; (void)out_size;

    // Kernel 1: plain launch.
    sort_chunk_kernel<<<BB * NCHUNK, CHUNK>>>(sig);

    // Kernels 2 & 3: programmatic dependent launch — grid setup overlaps the
    // predecessor's drain; device-side sync gates the actual dependency.
    cudaLaunchAttribute attr[1];
    attr[0].id = cudaLaunchAttributeProgrammaticStreamSerialization;
    attr[0].val.programmaticStreamSerializationAllowed = 1;

    {
        cudaLaunchConfig_t cfg = {};
        cfg.gridDim  = dim3(BB * NCHUNK);
        cfg.blockDim = dim3(CHUNK);
        cfg.stream   = 0;
        cfg.attrs    = attr;
        cfg.numAttrs = 1;
        cudaLaunchKernelEx(&cfg, rank_merge_kernel);
    }
    {
        cudaLaunchConfig_t cfg = {};
        cfg.gridDim  = dim3(BB * (KK + 1) / ROWS_PER_BLK);
        cfg.blockDim = dim3(192);
        cfg.stream   = 0;
        cfg.attrs    = attr;
        cfg.numAttrs = 1;
        cudaLaunchKernelEx(&cfg, gather_kernel, (const float4*)x, (float4*)d_out);
    }
}